// round 14
// baseline (speedup 1.0000x reference)
#include <cuda_runtime.h>
#include <cuda_fp16.h>
#include <cstdint>

#define BATCH 8192
#define IND   1024
#define OUTD  1024
#define DD    8
#define TM    64
#define TN    64
#define KC    64
#define NIC   16
#define NPAIRS 64
#define NTHREADS 128

// SMEM: 2 pair-buffers (each 2x8KB tiles) + bias + mbarriers
#define SM_B     0
#define SM_BIAS  32768
#define SM_MBAR  34816
#define SM_ALLOC 34880

__device__ __half g_wh[(size_t)DD * OUTD * IND];
__device__ __half g_ih[(size_t)BATCH * IND];

static __device__ __forceinline__ uint32_t smem_u32(const void* p) {
    uint32_t a;
    asm("{ .reg .u64 t; cvta.to.shared.u64 t, %1; cvt.u32.u64 %0, t; }" : "=r"(a) : "l"(p));
    return a;
}
static __device__ __forceinline__ void cp16(uint32_t dst, const void* src) {
    asm volatile("cp.async.cg.shared.global [%0], [%1], 16;" :: "r"(dst), "l"(src));
}
static __device__ __forceinline__ void cp_mbar_arrive(uint32_t mbar) {
    asm volatile("cp.async.mbarrier.arrive.noinc.shared.b64 [%0];" :: "r"(mbar) : "memory");
}
static __device__ __forceinline__ void mbar_arrive(uint32_t mbar) {
    asm volatile("mbarrier.arrive.shared.b64 _, [%0];" :: "r"(mbar) : "memory");
}
static __device__ __forceinline__ void mbar_wait(uint32_t mbar, uint32_t parity) {
    asm volatile(
        "{\n\t.reg .pred P;\n\t"
        "L_%=:\n\t"
        "mbarrier.try_wait.parity.acquire.cta.shared::cta.b64 P, [%0], %1, 0x989680;\n\t"
        "@P bra.uni D_%=;\n\t"
        "bra.uni L_%=;\n\t"
        "D_%=:\n\t}"
        :: "r"(mbar), "r"(parity) : "memory");
}
static __device__ __forceinline__ void ldsm4(uint32_t* r, uint32_t addr) {
    asm volatile("ldmatrix.sync.aligned.m8n8.x4.shared.b16 {%0,%1,%2,%3}, [%4];"
                 : "=r"(r[0]), "=r"(r[1]), "=r"(r[2]), "=r"(r[3]) : "r"(addr));
}
static __device__ __forceinline__ void mma16816(float* c, uint32_t a0, uint32_t a1,
                                                uint32_t a2, uint32_t a3,
                                                uint32_t b0, uint32_t b1) {
    asm volatile("mma.sync.aligned.m16n8k16.row.col.f32.f16.f16.f32 "
                 "{%0,%1,%2,%3}, {%4,%5,%6,%7}, {%8,%9}, {%0,%1,%2,%3};"
                 : "+f"(c[0]), "+f"(c[1]), "+f"(c[2]), "+f"(c[3])
                 : "r"(a0), "r"(a1), "r"(a2), "r"(a3), "r"(b0), "r"(b1));
}
static __device__ __forceinline__ uint32_t hmul2u(uint32_t a, uint32_t b) {
    __half2 r = __hmul2(*reinterpret_cast<__half2*>(&a), *reinterpret_cast<__half2*>(&b));
    return *reinterpret_cast<uint32_t*>(&r);
}

// stage one 64n x 64k fp16 tile (swizzled 128B rows): 4 cp16/thread
static __device__ __forceinline__ void copy_b_tile(uint32_t dstbase, int tid,
                                                   const __half* wp) {
    #pragma unroll
    for (int j = 0; j < 4; j++) {
        int g = tid + j * NTHREADS;
        int n = g >> 3, c = g & 7;
        uint32_t off = (uint32_t)(n * 128 + c * 16);
        off ^= (uint32_t)((n & 7) << 4);
        cp16(dstbase + off, wp + (size_t)n * IND + c * 8);
    }
}

// fused prepass: weights AND input f32 -> f16
__global__ void dynlin_conv_kernel(const float* __restrict__ w,
                                   const float* __restrict__ inp) {
    size_t i = ((size_t)blockIdx.x * blockDim.x + threadIdx.x) * 4;
    float4 v = *reinterpret_cast<const float4*>(w + i);
    *reinterpret_cast<__half2*>(g_wh + i)     = __floats2half2_rn(v.x, v.y);
    *reinterpret_cast<__half2*>(g_wh + i + 2) = __floats2half2_rn(v.z, v.w);
    float4 u = *reinterpret_cast<const float4*>(inp + i);
    *reinterpret_cast<__half2*>(g_ih + i)     = __floats2half2_rn(u.x, u.y);
    *reinterpret_cast<__half2*>(g_ih + i + 2) = __floats2half2_rn(u.z, u.w);
}

__global__ void __launch_bounds__(NTHREADS, 3)
dynlin_main_kernel(const float* __restrict__ wv,
                   const float* __restrict__ biases,
                   float* __restrict__ out)
{
    extern __shared__ char sm[];
    const uint32_t sb = smem_u32(sm);
    const int tid  = threadIdx.x;
    const int lane = tid & 31;
    const int wid  = tid >> 5;          // 4 warps stacked in M (16 rows each)
    const int col0 = blockIdx.x * TN;
    const int row0 = blockIdx.y * TM;

    const uint32_t mb_full  = sb + SM_MBAR;
    const uint32_t mb_empty = sb + SM_MBAR + 16;

    if (tid == 0) {
        asm volatile("mbarrier.init.shared.b64 [%0], %1;" :: "r"(mb_full),      "r"(NTHREADS) : "memory");
        asm volatile("mbarrier.init.shared.b64 [%0], %1;" :: "r"(mb_full + 8),  "r"(NTHREADS) : "memory");
        asm volatile("mbarrier.init.shared.b64 [%0], %1;" :: "r"(mb_empty),     "r"(NTHREADS) : "memory");
        asm volatile("mbarrier.init.shared.b64 [%0], %1;" :: "r"(mb_empty + 8), "r"(NTHREADS) : "memory");
    }
    __syncthreads();

    // prologue fetch: pair 0 into buffer 0
    copy_b_tile(sb + SM_B, tid, g_wh + (size_t)col0 * IND);
    copy_b_tile(sb + SM_B + 8192, tid, g_wh + ((size_t)OUTD + col0) * IND);
    cp_mbar_arrive(mb_full);

    {   // bias tile [8][64]
        int d = tid >> 4, c = (tid & 15) * 4;
        float4 bv = *reinterpret_cast<const float4*>(biases + (size_t)d * OUTD + col0 + c);
        *reinterpret_cast<float4*>(sm + SM_BIAS + (d * TN + c) * 4) = bv;
    }

    float wr[2][8];                      // fp32 w for this thread's 2 acc rows
    #pragma unroll
    for (int rs = 0; rs < 2; rs++) {
        int r = row0 + wid * 16 + rs * 8 + (lane >> 2);
        float4 w0 = *reinterpret_cast<const float4*>(wv + (size_t)r * DD);
        float4 w1 = *reinterpret_cast<const float4*>(wv + (size_t)r * DD + 4);
        wr[rs][0]=w0.x; wr[rs][1]=w0.y; wr[rs][2]=w0.z; wr[rs][3]=w0.w;
        wr[rs][4]=w1.x; wr[rs][5]=w1.y; wr[rs][6]=w1.z; wr[rs][7]=w1.w;
    }

    float acc[8][4];
    #pragma unroll
    for (int nt = 0; nt < 8; nt++)
        #pragma unroll
        for (int k = 0; k < 4; k++) acc[nt][k] = 0.f;

    uint32_t inch[4][2][2];              // input half2 cache, refreshed per ic

    for (int ic = 0; ic < NIC; ic++) {
        const int i0 = ic * KC;
        #pragma unroll
        for (int rs = 0; rs < 2; rs++) {
            int r = row0 + wid * 16 + rs * 8 + (lane >> 2);
            const __half* ip = g_ih + (size_t)r * IND + i0 + (lane & 3) * 2;
            #pragma unroll
            for (int kb = 0; kb < 4; kb++)
                #pragma unroll
                for (int hs = 0; hs < 2; hs++)
                    inch[kb][rs][hs] =
                        *reinterpret_cast<const uint32_t*>(ip + kb * 16 + hs * 8);
        }

        #pragma unroll
        for (int jp = 0; jp < 4; jp++) {
            const int j  = ic * 4 + jp;
            const int pb = jp & 1;
            const uint32_t pf = (uint32_t)((jp >> 1) & 1);                 // full[pb]
            const uint32_t pe = (uint32_t)((jp == 0 || jp == 3) ? 1 : 0);  // empty[pb^1]

            uint32_t whd[2][2];
            #pragma unroll
            for (int half = 0; half < 2; half++)
                #pragma unroll
                for (int rs = 0; rs < 2; rs++) {
                    __half2 h = __half2half2(__float2half_rn(wr[rs][jp * 2 + half]));
                    whd[half][rs] = *reinterpret_cast<uint32_t*>(&h);
                }

            // producer: fetch pair j+1 into buffer pb^1
            if (j + 1 < NPAIRS) {
                if (j >= 1) mbar_wait(mb_empty + (uint32_t)(pb ^ 1) * 8, pe);
                const int sn = 2 * (j + 1);
                const int nd = sn & 7, nic = sn >> 3;
                const __half* wp0 = g_wh + ((size_t)nd * OUTD + col0) * IND + nic * KC;
                const uint32_t nb = sb + SM_B + (uint32_t)(pb ^ 1) * 16384;
                copy_b_tile(nb, tid, wp0);
                copy_b_tile(nb + 8192, tid, wp0 + (size_t)OUTD * IND);
                cp_mbar_arrive(mb_full + (uint32_t)(pb ^ 1) * 8);
            }

            // consumer: wait pair j data
            mbar_wait(mb_full + (uint32_t)pb * 8, pf);

            #pragma unroll
            for (int half = 0; half < 2; half++) {
                const uint32_t bbase = sb + SM_B + (uint32_t)pb * 16384
                                     + (uint32_t)half * 8192;
                #pragma unroll
                for (int kb = 0; kb < 4; kb++) {
                    uint32_t bf[16];
                    #pragma unroll
                    for (int pr = 0; pr < 4; pr++) {
                        int n = pr * 16 + (lane & 7) + ((lane >> 4) << 3);
                        uint32_t off = (uint32_t)(n * 128 + kb * 32 + ((lane >> 3) & 1) * 16);
                        off ^= (uint32_t)((n & 7) << 4);
                        ldsm4(bf + pr * 4, bbase + off);
                    }
                    if (half == 1 && kb == 3)
                        mbar_arrive(mb_empty + (uint32_t)pb * 8);

                    uint32_t a0 = hmul2u(inch[kb][0][0], whd[half][0]);
                    uint32_t a1 = hmul2u(inch[kb][1][0], whd[half][1]);
                    uint32_t a2 = hmul2u(inch[kb][0][1], whd[half][0]);
                    uint32_t a3 = hmul2u(inch[kb][1][1], whd[half][1]);
                    #pragma unroll
                    for (int nt = 0; nt < 8; nt++) {
                        int bi = (nt >> 1) * 4 + (nt & 1) * 2;
                        mma16816(acc[nt], a0, a1, a2, a3, bf[bi], bf[bi + 1]);
                    }
                }
            }
        }
    }

    __syncthreads();

    // epilogue: out = acc + sum_d w[row,d]*biases[d,col]
    #pragma unroll
    for (int nt = 0; nt < 8; nt++) {
        int coff = nt * 8 + (lane & 3) * 2;
        float2 bv[8];
        #pragma unroll
        for (int d = 0; d < DD; d++)
            bv[d] = *reinterpret_cast<const float2*>(sm + SM_BIAS + (d * TN + coff) * 4);
        #pragma unroll
        for (int rs = 0; rs < 2; rs++) {
            float s0 = 0.f, s1 = 0.f;
            #pragma unroll
            for (int d = 0; d < DD; d++) {
                s0 = fmaf(wr[rs][d], bv[d].x, s0);
                s1 = fmaf(wr[rs][d], bv[d].y, s1);
            }
            int r = row0 + wid * 16 + rs * 8 + (lane >> 2);
            float2 o;
            o.x = acc[nt][rs * 2 + 0] + s0;
            o.y = acc[nt][rs * 2 + 1] + s1;
            *reinterpret_cast<float2*>(out + (size_t)r * OUTD + col0 + coff) = o;
        }
    }
}

extern "C" void kernel_launch(void* const* d_in, const int* in_sizes, int n_in,
                              void* d_out, int out_size) {
    const float* input = nullptr;
    const float* wv = nullptr;
    const float* weights = nullptr;
    const float* biases = nullptr;
    for (int i = 0; i < n_in; i++) {
        long long sz = in_sizes[i];
        if (sz == (long long)BATCH * DD)           wv = (const float*)d_in[i];
        else if (sz == (long long)DD * OUTD)       biases = (const float*)d_in[i];
        else if (sz == (long long)BATCH * IND) {
            if (!input) input = (const float*)d_in[i];
            else        weights = (const float*)d_in[i];
        }
    }
    float* out = (float*)d_out;

    dynlin_conv_kernel<<<(DD * OUTD * IND) / (256 * 4), 256>>>(weights, input);

    cudaFuncSetAttribute(dynlin_main_kernel,
                         cudaFuncAttributeMaxDynamicSharedMemorySize, SM_ALLOC);
    dim3 grid(OUTD / TN, BATCH / TM);
    dynlin_main_kernel<<<grid, NTHREADS, SM_ALLOC>>>(wv, biases, out);
}

// round 15
// speedup vs baseline: 1.0311x; 1.0311x over previous
#include <cuda_runtime.h>
#include <cuda_fp16.h>
#include <cstdint>

#define BATCH 8192
#define IND   1024
#define OUTD  1024
#define DD    8
#define TM    64
#define TN    128
#define KC    64
#define NIC   16
#define NPAIRS 64
#define NTHREADS 128

// SMEM: 3 pair-buffers (each 2x16KB tiles) + bias + mbarriers
#define SM_B     0
#define SM_BIAS  98304
#define SM_MBAR  102400         // full[0..2], empty[0..2]
#define SM_ALLOC 102464

__device__ __half g_wh[(size_t)DD * OUTD * IND];

static __device__ __forceinline__ uint32_t smem_u32(const void* p) {
    uint32_t a;
    asm("{ .reg .u64 t; cvta.to.shared.u64 t, %1; cvt.u32.u64 %0, t; }" : "=r"(a) : "l"(p));
    return a;
}
static __device__ __forceinline__ void cp16(uint32_t dst, const void* src) {
    asm volatile("cp.async.cg.shared.global [%0], [%1], 16;" :: "r"(dst), "l"(src));
}
static __device__ __forceinline__ void cp_mbar_arrive(uint32_t mbar) {
    asm volatile("cp.async.mbarrier.arrive.noinc.shared.b64 [%0];" :: "r"(mbar) : "memory");
}
static __device__ __forceinline__ void mbar_arrive(uint32_t mbar) {
    asm volatile("mbarrier.arrive.shared.b64 _, [%0];" :: "r"(mbar) : "memory");
}
static __device__ __forceinline__ void mbar_wait(uint32_t mbar, uint32_t parity) {
    asm volatile(
        "{\n\t.reg .pred P;\n\t"
        "L_%=:\n\t"
        "mbarrier.try_wait.parity.acquire.cta.shared::cta.b64 P, [%0], %1, 0x989680;\n\t"
        "@P bra.uni D_%=;\n\t"
        "bra.uni L_%=;\n\t"
        "D_%=:\n\t}"
        :: "r"(mbar), "r"(parity) : "memory");
}
static __device__ __forceinline__ void ldsm4(uint32_t* r, uint32_t addr) {
    asm volatile("ldmatrix.sync.aligned.m8n8.x4.shared.b16 {%0,%1,%2,%3}, [%4];"
                 : "=r"(r[0]), "=r"(r[1]), "=r"(r[2]), "=r"(r[3]) : "r"(addr));
}
static __device__ __forceinline__ void mma16816(float* c, uint32_t a0, uint32_t a1,
                                                uint32_t a2, uint32_t a3,
                                                uint32_t b0, uint32_t b1) {
    asm volatile("mma.sync.aligned.m16n8k16.row.col.f32.f16.f16.f32 "
                 "{%0,%1,%2,%3}, {%4,%5,%6,%7}, {%8,%9}, {%0,%1,%2,%3};"
                 : "+f"(c[0]), "+f"(c[1]), "+f"(c[2]), "+f"(c[3])
                 : "r"(a0), "r"(a1), "r"(a2), "r"(a3), "r"(b0), "r"(b1));
}
static __device__ __forceinline__ uint32_t packh2(float x, float y) {
    __half2 h = __floats2half2_rn(x, y);
    return *reinterpret_cast<uint32_t*>(&h);
}
static __device__ __forceinline__ uint32_t hmul2u(uint32_t a, uint32_t b) {
    __half2 r = __hmul2(*reinterpret_cast<__half2*>(&a), *reinterpret_cast<__half2*>(&b));
    return *reinterpret_cast<uint32_t*>(&r);
}

// stage one 128n x 64k fp16 tile (swizzled 128B rows): 8 cp16/thread
static __device__ __forceinline__ void copy_b_tile(uint32_t dstbase, int tid,
                                                   const __half* wp) {
    #pragma unroll
    for (int j = 0; j < 8; j++) {
        int g = tid + j * NTHREADS;
        int n = g >> 3, c = g & 7;
        uint32_t off = (uint32_t)(n * 128 + c * 16);
        off ^= (uint32_t)((n & 7) << 4);
        cp16(dstbase + off, wp + (size_t)n * IND + c * 8);
    }
}

__global__ void dynlin_wconv_kernel(const float* __restrict__ w) {
    size_t i = ((size_t)blockIdx.x * blockDim.x + threadIdx.x) * 4;
    float4 v = *reinterpret_cast<const float4*>(w + i);
    *reinterpret_cast<__half2*>(g_wh + i)     = __floats2half2_rn(v.x, v.y);
    *reinterpret_cast<__half2*>(g_wh + i + 2) = __floats2half2_rn(v.z, v.w);
}

__global__ void __launch_bounds__(NTHREADS, 2)
dynlin_main_kernel(const float* __restrict__ input,
                   const float* __restrict__ wv,
                   const float* __restrict__ biases,
                   float* __restrict__ out)
{
    extern __shared__ char sm[];
    const uint32_t sb = smem_u32(sm);
    const int tid  = threadIdx.x;
    const int lane = tid & 31;
    const int wid  = tid >> 5;
    const int wm   = wid & 1;          // 2 warp rows x 32
    const int wn   = wid >> 1;         // 2 warp cols x 64
    const int col0 = blockIdx.x * TN;
    const int row0 = blockIdx.y * TM;

    const uint32_t mb_full  = sb + SM_MBAR;       // full[0..2]
    const uint32_t mb_empty = sb + SM_MBAR + 24;  // empty[0..2]

    if (tid == 0) {
        #pragma unroll
        for (int s = 0; s < 3; s++) {
            asm volatile("mbarrier.init.shared.b64 [%0], %1;" :: "r"(mb_full  + s * 8), "r"(NTHREADS) : "memory");
            asm volatile("mbarrier.init.shared.b64 [%0], %1;" :: "r"(mb_empty + s * 8), "r"(NTHREADS) : "memory");
        }
    }
    __syncthreads();   // mbarrier init visible

    // prologue: pairs 0 and 1 into stages 0 and 1
    copy_b_tile(sb + SM_B, tid, g_wh + (size_t)col0 * IND);
    copy_b_tile(sb + SM_B + 16384, tid, g_wh + ((size_t)OUTD + col0) * IND);
    cp_mbar_arrive(mb_full);
    {
        const __half* wp0 = g_wh + ((size_t)2 * OUTD + col0) * IND;  // d=2,3 ic=0
        copy_b_tile(sb + SM_B + 32768, tid, wp0);
        copy_b_tile(sb + SM_B + 49152, tid, wp0 + (size_t)OUTD * IND);
        cp_mbar_arrive(mb_full + 8);
    }

    {   // bias tile [8][128]
        int d = tid >> 4, c = (tid & 15) * 8;
        float4 b0 = *reinterpret_cast<const float4*>(biases + (size_t)d * OUTD + col0 + c);
        float4 b1 = *reinterpret_cast<const float4*>(biases + (size_t)d * OUTD + col0 + c + 4);
        *reinterpret_cast<float4*>(sm + SM_BIAS + (d * TN + c) * 4)     = b0;
        *reinterpret_cast<float4*>(sm + SM_BIAS + (d * TN + c + 4) * 4) = b1;
    }

    float wr[2][2][8];
    #pragma unroll
    for (int mt = 0; mt < 2; mt++)
        #pragma unroll
        for (int rs = 0; rs < 2; rs++) {
            int r = row0 + wm * 32 + mt * 16 + rs * 8 + (lane >> 2);
            float4 w0 = *reinterpret_cast<const float4*>(wv + (size_t)r * DD);
            float4 w1 = *reinterpret_cast<const float4*>(wv + (size_t)r * DD + 4);
            wr[mt][rs][0]=w0.x; wr[mt][rs][1]=w0.y; wr[mt][rs][2]=w0.z; wr[mt][rs][3]=w0.w;
            wr[mt][rs][4]=w1.x; wr[mt][rs][5]=w1.y; wr[mt][rs][6]=w1.z; wr[mt][rs][7]=w1.w;
        }

    float acc[2][8][4];
    #pragma unroll
    for (int mt = 0; mt < 2; mt++)
        #pragma unroll
        for (int nt = 0; nt < 8; nt++)
            #pragma unroll
            for (int k = 0; k < 4; k++) acc[mt][nt][k] = 0.f;

    uint32_t inch[2][4][2][2];   // input as half2, refreshed per ic

    for (int ic = 0; ic < NIC; ic++) {
        const int i0 = ic * KC;
        #pragma unroll
        for (int mt = 0; mt < 2; mt++)
            #pragma unroll
            for (int rs = 0; rs < 2; rs++) {
                int r = row0 + wm * 32 + mt * 16 + rs * 8 + (lane >> 2);
                const float* ip = input + (size_t)r * IND + i0 + (lane & 3) * 2;
                #pragma unroll
                for (int kb = 0; kb < 4; kb++)
                    #pragma unroll
                    for (int hs = 0; hs < 2; hs++) {
                        float2 v = *reinterpret_cast<const float2*>(ip + kb * 16 + hs * 8);
                        inch[mt][kb][rs][hs] = packh2(v.x, v.y);
                    }
            }

        #pragma unroll
        for (int jp = 0; jp < 4; jp++) {
            const int j  = ic * 4 + jp;
            // 3-stage ring bookkeeping (runtime; outside the hot loop)
            const int      cs = j % 3;                       // consumer stage
            const uint32_t pf = (uint32_t)((j / 3) & 1);     // full[cs] parity

            uint32_t whd[2][2][2];
            #pragma unroll
            for (int half = 0; half < 2; half++)
                #pragma unroll
                for (int mt = 0; mt < 2; mt++)
                    #pragma unroll
                    for (int rs = 0; rs < 2; rs++) {
                        __half2 h = __half2half2(__float2half_rn(wr[mt][rs][jp * 2 + half]));
                        whd[half][mt][rs] = *reinterpret_cast<uint32_t*>(&h);
                    }

            // producer: fetch pair j+2 into stage (j+2)%3
            const int jf = j + 2;
            if (jf < NPAIRS) {
                const int sf = jf % 3;
                if (jf >= 3) {
                    const uint32_t pe = (uint32_t)(((jf / 3) - 1) & 1);
                    mbar_wait(mb_empty + (uint32_t)sf * 8, pe);
                }
                const int sn = 2 * jf;
                const int nd = sn & 7, nic = sn >> 3;
                const __half* wp0 = g_wh + ((size_t)nd * OUTD + col0) * IND + nic * KC;
                const uint32_t nb = sb + SM_B + (uint32_t)sf * 32768;
                copy_b_tile(nb, tid, wp0);
                copy_b_tile(nb + 16384, tid, wp0 + (size_t)OUTD * IND);
                cp_mbar_arrive(mb_full + (uint32_t)sf * 8);
            }

            // consumer: wait pair j data
            mbar_wait(mb_full + (uint32_t)cs * 8, pf);

            #pragma unroll
            for (int half = 0; half < 2; half++) {
                const uint32_t bbase = sb + SM_B + (uint32_t)cs * 32768
                                     + (uint32_t)half * 16384;
                #pragma unroll
                for (int kb = 0; kb < 4; kb++) {
                    uint32_t bf[16];
                    #pragma unroll
                    for (int pr = 0; pr < 4; pr++) {
                        int n = wn * 64 + pr * 16 + (lane & 7) + ((lane >> 4) << 3);
                        uint32_t off = (uint32_t)(n * 128 + kb * 32 + ((lane >> 3) & 1) * 16);
                        off ^= (uint32_t)((n & 7) << 4);
                        ldsm4(bf + pr * 4, bbase + off);
                    }
                    #pragma unroll
                    for (int mt = 0; mt < 2; mt++) {
                        uint32_t a0 = hmul2u(inch[mt][kb][0][0], whd[half][mt][0]);
                        uint32_t a1 = hmul2u(inch[mt][kb][1][0], whd[half][mt][1]);
                        uint32_t a2 = hmul2u(inch[mt][kb][0][1], whd[half][mt][0]);
                        uint32_t a3 = hmul2u(inch[mt][kb][1][1], whd[half][mt][1]);
                        #pragma unroll
                        for (int nt = 0; nt < 8; nt++) {
                            int bi = (nt >> 1) * 4 + (nt & 1) * 2;
                            mma16816(acc[mt][nt], a0, a1, a2, a3, bf[bi], bf[bi + 1]);
                        }
                    }
                }
            }

            // reads of pair j done -> stage cs reusable
            mbar_arrive(mb_empty + (uint32_t)cs * 8);
        }
    }

    __syncthreads();

    // epilogue: out = acc + sum_d w[row,d]*biases[d,col]
    #pragma unroll
    for (int nt = 0; nt < 8; nt++) {
        int coff = wn * 64 + nt * 8 + (lane & 3) * 2;
        float2 bv[8];
        #pragma unroll
        for (int d = 0; d < DD; d++)
            bv[d] = *reinterpret_cast<const float2*>(sm + SM_BIAS + (d * TN + coff) * 4);
        #pragma unroll
        for (int mt = 0; mt < 2; mt++)
            #pragma unroll
            for (int rs = 0; rs < 2; rs++) {
                float s0 = 0.f, s1 = 0.f;
                #pragma unroll
                for (int d = 0; d < DD; d++) {
                    s0 = fmaf(wr[mt][rs][d], bv[d].x, s0);
                    s1 = fmaf(wr[mt][rs][d], bv[d].y, s1);
                }
                int r = row0 + wm * 32 + mt * 16 + rs * 8 + (lane >> 2);
                float2 o;
                o.x = acc[mt][nt][rs * 2 + 0] + s0;
                o.y = acc[mt][nt][rs * 2 + 1] + s1;
                *reinterpret_cast<float2*>(out + (size_t)r * OUTD + col0 + coff) = o;
            }
    }
}

extern "C" void kernel_launch(void* const* d_in, const int* in_sizes, int n_in,
                              void* d_out, int out_size) {
    const float* input = nullptr;
    const float* wv = nullptr;
    const float* weights = nullptr;
    const float* biases = nullptr;
    for (int i = 0; i < n_in; i++) {
        long long sz = in_sizes[i];
        if (sz == (long long)BATCH * DD)           wv = (const float*)d_in[i];
        else if (sz == (long long)DD * OUTD)       biases = (const float*)d_in[i];
        else if (sz == (long long)BATCH * IND) {
            if (!input) input = (const float*)d_in[i];
            else        weights = (const float*)d_in[i];
        }
    }
    float* out = (float*)d_out;

    dynlin_wconv_kernel<<<(DD * OUTD * IND) / (256 * 4), 256>>>(weights);

    cudaFuncSetAttribute(dynlin_main_kernel,
                         cudaFuncAttributeMaxDynamicSharedMemorySize, SM_ALLOC);
    dim3 grid(OUTD / TN, BATCH / TM);
    dynlin_main_kernel<<<grid, NTHREADS, SM_ALLOC>>>(input, wv, biases, out);
}

// round 16
// speedup vs baseline: 1.1601x; 1.1251x over previous
#include <cuda_runtime.h>
#include <cuda_fp16.h>
#include <cstdint>

#define BATCH 8192
#define IND   1024
#define OUTD  1024
#define DD    8
#define TM    64
#define TN    128
#define KC    64
#define NIC   16
#define NPAIRS 64
#define NTHREADS 128

// SMEM: 2 pair-buffers (each 32KB contiguous) + bias + mbarriers
#define SM_B     0
#define SM_BIAS  65536
#define SM_MBAR  69632          // full[0],full[1],empty[0],empty[1]
#define SM_ALLOC 69696

// tile-major, pre-swizzled fp16 weights:
// pair-block p = (nic*4 + d/2)*8 + colTile  (32KB each: tiles d, d+1)
__device__ __half g_wt[(size_t)DD * OUTD * IND];

static __device__ __forceinline__ uint32_t smem_u32(const void* p) {
    uint32_t a;
    asm("{ .reg .u64 t; cvta.to.shared.u64 t, %1; cvt.u32.u64 %0, t; }" : "=r"(a) : "l"(p));
    return a;
}
static __device__ __forceinline__ void mbar_expect_tx(uint32_t mbar, uint32_t bytes) {
    asm volatile("mbarrier.arrive.expect_tx.shared.b64 _, [%0], %1;"
                 :: "r"(mbar), "r"(bytes) : "memory");
}
static __device__ __forceinline__ void bulk_cp(uint32_t dst, const void* src,
                                               uint32_t bytes, uint32_t mbar) {
    asm volatile("cp.async.bulk.shared::cluster.global.mbarrier::complete_tx::bytes "
                 "[%0], [%1], %2, [%3];"
                 :: "r"(dst), "l"(src), "r"(bytes), "r"(mbar) : "memory");
}
static __device__ __forceinline__ void mbar_arrive(uint32_t mbar) {
    asm volatile("mbarrier.arrive.shared.b64 _, [%0];" :: "r"(mbar) : "memory");
}
static __device__ __forceinline__ void mbar_wait(uint32_t mbar, uint32_t parity) {
    asm volatile(
        "{\n\t.reg .pred P;\n\t"
        "L_%=:\n\t"
        "mbarrier.try_wait.parity.acquire.cta.shared::cta.b64 P, [%0], %1, 0x989680;\n\t"
        "@P bra.uni D_%=;\n\t"
        "bra.uni L_%=;\n\t"
        "D_%=:\n\t}"
        :: "r"(mbar), "r"(parity) : "memory");
}
static __device__ __forceinline__ void ldsm4(uint32_t* r, uint32_t addr) {
    asm volatile("ldmatrix.sync.aligned.m8n8.x4.shared.b16 {%0,%1,%2,%3}, [%4];"
                 : "=r"(r[0]), "=r"(r[1]), "=r"(r[2]), "=r"(r[3]) : "r"(addr));
}
static __device__ __forceinline__ void mma16816(float* c, uint32_t a0, uint32_t a1,
                                                uint32_t a2, uint32_t a3,
                                                uint32_t b0, uint32_t b1) {
    asm volatile("mma.sync.aligned.m16n8k16.row.col.f32.f16.f16.f32 "
                 "{%0,%1,%2,%3}, {%4,%5,%6,%7}, {%8,%9}, {%0,%1,%2,%3};"
                 : "+f"(c[0]), "+f"(c[1]), "+f"(c[2]), "+f"(c[3])
                 : "r"(a0), "r"(a1), "r"(a2), "r"(a3), "r"(b0), "r"(b1));
}
static __device__ __forceinline__ uint32_t packh2(float x, float y) {
    __half2 h = __floats2half2_rn(x, y);
    return *reinterpret_cast<uint32_t*>(&h);
}
static __device__ __forceinline__ uint32_t hmul2u(uint32_t a, uint32_t b) {
    __half2 r = __hmul2(*reinterpret_cast<__half2*>(&a), *reinterpret_cast<__half2*>(&b));
    return *reinterpret_cast<uint32_t*>(&r);
}

// prepass: weights f32 -> f16, scattered into tile-major pre-swizzled layout
__global__ void dynlin_wconv_kernel(const float* __restrict__ w) {
    size_t idx4 = ((size_t)blockIdx.x * blockDim.x + threadIdx.x) * 4;
    float4 v = *reinterpret_cast<const float4*>(w + idx4);

    int d = (int)(idx4 >> 20);          // OUTD*IND = 2^20
    int o = (int)((idx4 >> 10) & 1023);
    int i = (int)(idx4 & 1023);
    int nic = i >> 6, cc = i & 63;
    int ct  = o >> 7, n  = o & 127;
    int dpair = d >> 1, dh = d & 1;

    int pairblk = (nic * 4 + dpair) * 8 + ct;
    size_t base = ((size_t)(pairblk * 2 + dh)) << 14;   // *16384 bytes
    uint32_t inner = (uint32_t)(n * 128 + ((cc >> 3) << 4) + ((cc & 7) * 2));
    inner ^= (uint32_t)((n & 7) << 4);

    __half2 h0 = __floats2half2_rn(v.x, v.y);
    __half2 h1 = __floats2half2_rn(v.z, v.w);
    uint2 pk;
    pk.x = *reinterpret_cast<uint32_t*>(&h0);
    pk.y = *reinterpret_cast<uint32_t*>(&h1);
    *reinterpret_cast<uint2*>(reinterpret_cast<char*>(g_wt) + base + inner) = pk;
}

__global__ void __launch_bounds__(NTHREADS, 2)
dynlin_main_kernel(const float* __restrict__ input,
                   const float* __restrict__ wv,
                   const float* __restrict__ biases,
                   float* __restrict__ out)
{
    extern __shared__ char sm[];
    const uint32_t sb = smem_u32(sm);
    const int tid  = threadIdx.x;
    const int lane = tid & 31;
    const int wid  = tid >> 5;
    const int wm   = wid & 1;          // 2 warp rows x 32
    const int wn   = wid >> 1;         // 2 warp cols x 64
    const int bx   = blockIdx.x;
    const int col0 = bx * TN;
    const int row0 = blockIdx.y * TM;

    const uint32_t mb_full  = sb + SM_MBAR;       // full[0], full[1] (tx-based, count 1)
    const uint32_t mb_empty = sb + SM_MBAR + 16;  // empty[0], empty[1] (count 128)

    if (tid == 0) {
        asm volatile("mbarrier.init.shared.b64 [%0], 1;"  :: "r"(mb_full)      : "memory");
        asm volatile("mbarrier.init.shared.b64 [%0], 1;"  :: "r"(mb_full + 8)  : "memory");
        asm volatile("mbarrier.init.shared.b64 [%0], %1;" :: "r"(mb_empty),     "r"(NTHREADS) : "memory");
        asm volatile("mbarrier.init.shared.b64 [%0], %1;" :: "r"(mb_empty + 8), "r"(NTHREADS) : "memory");
    }
    __syncthreads();   // init visible before any arrive/wait

    // prologue: pair 0 (pair-block 0*8+bx) into buffer 0, single bulk copy
    const char* wt0 = reinterpret_cast<const char*>(g_wt);
    if (tid == 0) {
        mbar_expect_tx(mb_full, 32768u);
        bulk_cp(sb + SM_B, wt0 + ((size_t)(0 * 8 + bx) << 15), 32768u, mb_full);
    }

    {   // bias tile [8][128]
        int d = tid >> 4, c = (tid & 15) * 8;
        float4 b0 = *reinterpret_cast<const float4*>(biases + (size_t)d * OUTD + col0 + c);
        float4 b1 = *reinterpret_cast<const float4*>(biases + (size_t)d * OUTD + col0 + c + 4);
        *reinterpret_cast<float4*>(sm + SM_BIAS + (d * TN + c) * 4)     = b0;
        *reinterpret_cast<float4*>(sm + SM_BIAS + (d * TN + c + 4) * 4) = b1;
    }

    float wr[2][2][8];
    #pragma unroll
    for (int mt = 0; mt < 2; mt++)
        #pragma unroll
        for (int rs = 0; rs < 2; rs++) {
            int r = row0 + wm * 32 + mt * 16 + rs * 8 + (lane >> 2);
            float4 w0 = *reinterpret_cast<const float4*>(wv + (size_t)r * DD);
            float4 w1 = *reinterpret_cast<const float4*>(wv + (size_t)r * DD + 4);
            wr[mt][rs][0]=w0.x; wr[mt][rs][1]=w0.y; wr[mt][rs][2]=w0.z; wr[mt][rs][3]=w0.w;
            wr[mt][rs][4]=w1.x; wr[mt][rs][5]=w1.y; wr[mt][rs][6]=w1.z; wr[mt][rs][7]=w1.w;
        }

    float acc[2][8][4];
    #pragma unroll
    for (int mt = 0; mt < 2; mt++)
        #pragma unroll
        for (int nt = 0; nt < 8; nt++)
            #pragma unroll
            for (int k = 0; k < 4; k++) acc[mt][nt][k] = 0.f;

    uint32_t inch[2][4][2][2];   // input as half2, refreshed per ic

    for (int ic = 0; ic < NIC; ic++) {
        const int i0 = ic * KC;
        #pragma unroll
        for (int mt = 0; mt < 2; mt++)
            #pragma unroll
            for (int rs = 0; rs < 2; rs++) {
                int r = row0 + wm * 32 + mt * 16 + rs * 8 + (lane >> 2);
                const float* ip = input + (size_t)r * IND + i0 + (lane & 3) * 2;
                #pragma unroll
                for (int kb = 0; kb < 4; kb++)
                    #pragma unroll
                    for (int hs = 0; hs < 2; hs++) {
                        float2 v = *reinterpret_cast<const float2*>(ip + kb * 16 + hs * 8);
                        inch[mt][kb][rs][hs] = packh2(v.x, v.y);
                    }
            }

        #pragma unroll
        for (int jp = 0; jp < 4; jp++) {
            const int j  = ic * 4 + jp;
            const int pb = jp & 1;
            const uint32_t pf = (uint32_t)((jp >> 1) & 1);                 // full[pb]
            const uint32_t pe = (uint32_t)((jp == 0 || jp == 3) ? 1 : 0);  // empty[pb^1]

            uint32_t whd[2][2][2];
            #pragma unroll
            for (int half = 0; half < 2; half++)
                #pragma unroll
                for (int mt = 0; mt < 2; mt++)
                    #pragma unroll
                    for (int rs = 0; rs < 2; rs++) {
                        __half2 h = __half2half2(__float2half_rn(wr[mt][rs][jp * 2 + half]));
                        whd[half][mt][rs] = *reinterpret_cast<uint32_t*>(&h);
                    }

            // producer (elected): fetch pair j+1 into buffer pb^1, one bulk copy
            if (tid == 0 && j + 1 < NPAIRS) {
                const int jj = j + 1;
                if (j >= 1) mbar_wait(mb_empty + (uint32_t)(pb ^ 1) * 8, pe);
                const uint32_t fb = mb_full + (uint32_t)(pb ^ 1) * 8;
                mbar_expect_tx(fb, 32768u);
                bulk_cp(sb + SM_B + (uint32_t)(pb ^ 1) * 32768,
                        wt0 + ((size_t)(jj * 8 + bx) << 15), 32768u, fb);
            }

            // consumer: wait pair j data
            mbar_wait(mb_full + (uint32_t)pb * 8, pf);

            #pragma unroll
            for (int half = 0; half < 2; half++) {
                const uint32_t bbase = sb + SM_B + (uint32_t)pb * 32768
                                     + (uint32_t)half * 16384;
                #pragma unroll
                for (int kb = 0; kb < 4; kb++) {
                    uint32_t bf[16];
                    #pragma unroll
                    for (int pr = 0; pr < 4; pr++) {
                        int n = wn * 64 + pr * 16 + (lane & 7) + ((lane >> 4) << 3);
                        uint32_t off = (uint32_t)(n * 128 + kb * 32 + ((lane >> 3) & 1) * 16);
                        off ^= (uint32_t)((n & 7) << 4);
                        ldsm4(bf + pr * 4, bbase + off);
                    }
                    #pragma unroll
                    for (int mt = 0; mt < 2; mt++) {
                        uint32_t a0 = hmul2u(inch[mt][kb][0][0], whd[half][mt][0]);
                        uint32_t a1 = hmul2u(inch[mt][kb][1][0], whd[half][mt][1]);
                        uint32_t a2 = hmul2u(inch[mt][kb][0][1], whd[half][mt][0]);
                        uint32_t a3 = hmul2u(inch[mt][kb][1][1], whd[half][mt][1]);
                        #pragma unroll
                        for (int nt = 0; nt < 8; nt++) {
                            int bi = (nt >> 1) * 4 + (nt & 1) * 2;
                            mma16816(acc[mt][nt], a0, a1, a2, a3, bf[bi], bf[bi + 1]);
                        }
                    }
                }
            }

            // reads of pair j done
            mbar_arrive(mb_empty + (uint32_t)pb * 8);
        }
    }

    __syncthreads();

    // epilogue: out = acc + sum_d w[row,d]*biases[d,col]
    #pragma unroll
    for (int nt = 0; nt < 8; nt++) {
        int coff = wn * 64 + nt * 8 + (lane & 3) * 2;
        float2 bv[8];
        #pragma unroll
        for (int d = 0; d < DD; d++)
            bv[d] = *reinterpret_cast<const float2*>(sm + SM_BIAS + (d * TN + coff) * 4);
        #pragma unroll
        for (int mt = 0; mt < 2; mt++)
            #pragma unroll
            for (int rs = 0; rs < 2; rs++) {
                float s0 = 0.f, s1 = 0.f;
                #pragma unroll
                for (int d = 0; d < DD; d++) {
                    s0 = fmaf(wr[mt][rs][d], bv[d].x, s0);
                    s1 = fmaf(wr[mt][rs][d], bv[d].y, s1);
                }
                int r = row0 + wm * 32 + mt * 16 + rs * 8 + (lane >> 2);
                float2 o;
                o.x = acc[mt][nt][rs * 2 + 0] + s0;
                o.y = acc[mt][nt][rs * 2 + 1] + s1;
                *reinterpret_cast<float2*>(out + (size_t)r * OUTD + col0 + coff) = o;
            }
    }
}

extern "C" void kernel_launch(void* const* d_in, const int* in_sizes, int n_in,
                              void* d_out, int out_size) {
    const float* input = nullptr;
    const float* wv = nullptr;
    const float* weights = nullptr;
    const float* biases = nullptr;
    for (int i = 0; i < n_in; i++) {
        long long sz = in_sizes[i];
        if (sz == (long long)BATCH * DD)           wv = (const float*)d_in[i];
        else if (sz == (long long)DD * OUTD)       biases = (const float*)d_in[i];
        else if (sz == (long long)BATCH * IND) {
            if (!input) input = (const float*)d_in[i];
            else        weights = (const float*)d_in[i];
        }
    }
    float* out = (float*)d_out;

    dynlin_wconv_kernel<<<(DD * OUTD * IND) / (256 * 4), 256>>>(weights);

    cudaFuncSetAttribute(dynlin_main_kernel,
                         cudaFuncAttributeMaxDynamicSharedMemorySize, SM_ALLOC);
    dim3 grid(OUTD / TN, BATCH / TM);
    dynlin_main_kernel<<<grid, NTHREADS, SM_ALLOC>>>(input, wv, biases, out);
}

// round 17
// speedup vs baseline: 1.1755x; 1.0133x over previous
#include <cuda_runtime.h>
#include <cuda_fp16.h>
#include <cstdint>

#define BATCH 8192
#define IND   1024
#define OUTD  1024
#define DD    8
#define TM    64
#define TN    128
#define KC    64
#define NIC   16
#define NPAIRS 64
#define NTHREADS 128

// SMEM: 2 pair-buffers (each 32KB contiguous) + bias + mbarriers
#define SM_B     0
#define SM_BIAS  65536
#define SM_MBAR  69632          // full[0],full[1],empty[0],empty[1]
#define SM_ALLOC 69696

// tile-major, pre-swizzled fp16 weights:
// pair-block p = (nic*4 + d/2)*8 + colTile  (32KB each: tiles d, d+1)
__device__ __half g_wt[(size_t)DD * OUTD * IND];
__device__ __half g_ih[(size_t)BATCH * IND];

static __device__ __forceinline__ uint32_t smem_u32(const void* p) {
    uint32_t a;
    asm("{ .reg .u64 t; cvta.to.shared.u64 t, %1; cvt.u32.u64 %0, t; }" : "=r"(a) : "l"(p));
    return a;
}
static __device__ __forceinline__ void mbar_expect_tx(uint32_t mbar, uint32_t bytes) {
    asm volatile("mbarrier.arrive.expect_tx.shared.b64 _, [%0], %1;"
                 :: "r"(mbar), "r"(bytes) : "memory");
}
static __device__ __forceinline__ void bulk_cp(uint32_t dst, const void* src,
                                               uint32_t bytes, uint32_t mbar) {
    asm volatile("cp.async.bulk.shared::cluster.global.mbarrier::complete_tx::bytes "
                 "[%0], [%1], %2, [%3];"
                 :: "r"(dst), "l"(src), "r"(bytes), "r"(mbar) : "memory");
}
static __device__ __forceinline__ void mbar_arrive(uint32_t mbar) {
    asm volatile("mbarrier.arrive.shared.b64 _, [%0];" :: "r"(mbar) : "memory");
}
static __device__ __forceinline__ void mbar_wait(uint32_t mbar, uint32_t parity) {
    asm volatile(
        "{\n\t.reg .pred P;\n\t"
        "L_%=:\n\t"
        "mbarrier.try_wait.parity.acquire.cta.shared::cta.b64 P, [%0], %1, 0x989680;\n\t"
        "@P bra.uni D_%=;\n\t"
        "bra.uni L_%=;\n\t"
        "D_%=:\n\t}"
        :: "r"(mbar), "r"(parity) : "memory");
}
static __device__ __forceinline__ void ldsm4(uint32_t* r, uint32_t addr) {
    asm volatile("ldmatrix.sync.aligned.m8n8.x4.shared.b16 {%0,%1,%2,%3}, [%4];"
                 : "=r"(r[0]), "=r"(r[1]), "=r"(r[2]), "=r"(r[3]) : "r"(addr));
}
static __device__ __forceinline__ void mma16816(float* c, uint32_t a0, uint32_t a1,
                                                uint32_t a2, uint32_t a3,
                                                uint32_t b0, uint32_t b1) {
    asm volatile("mma.sync.aligned.m16n8k16.row.col.f32.f16.f16.f32 "
                 "{%0,%1,%2,%3}, {%4,%5,%6,%7}, {%8,%9}, {%0,%1,%2,%3};"
                 : "+f"(c[0]), "+f"(c[1]), "+f"(c[2]), "+f"(c[3])
                 : "r"(a0), "r"(a1), "r"(a2), "r"(a3), "r"(b0), "r"(b1));
}
static __device__ __forceinline__ uint32_t hmul2u(uint32_t a, uint32_t b) {
    __half2 r = __hmul2(*reinterpret_cast<__half2*>(&a), *reinterpret_cast<__half2*>(&b));
    return *reinterpret_cast<uint32_t*>(&r);
}

// prepass: weights f32 -> f16 (tile-major pre-swizzled) AND input f32 -> f16
__global__ void dynlin_prep_kernel(const float* __restrict__ w,
                                   const float* __restrict__ inp) {
    size_t idx4 = ((size_t)blockIdx.x * blockDim.x + threadIdx.x) * 4;
    float4 v = *reinterpret_cast<const float4*>(w + idx4);

    int d = (int)(idx4 >> 20);          // OUTD*IND = 2^20
    int o = (int)((idx4 >> 10) & 1023);
    int i = (int)(idx4 & 1023);
    int nic = i >> 6, cc = i & 63;
    int ct  = o >> 7, n  = o & 127;
    int dpair = d >> 1, dh = d & 1;

    int pairblk = (nic * 4 + dpair) * 8 + ct;
    size_t base = ((size_t)(pairblk * 2 + dh)) << 14;   // *16384 bytes
    uint32_t inner = (uint32_t)(n * 128 + ((cc >> 3) << 4) + ((cc & 7) * 2));
    inner ^= (uint32_t)((n & 7) << 4);

    __half2 h0 = __floats2half2_rn(v.x, v.y);
    __half2 h1 = __floats2half2_rn(v.z, v.w);
    uint2 pk;
    pk.x = *reinterpret_cast<uint32_t*>(&h0);
    pk.y = *reinterpret_cast<uint32_t*>(&h1);
    *reinterpret_cast<uint2*>(reinterpret_cast<char*>(g_wt) + base + inner) = pk;

    // input: same element count, linear convert
    float4 u = *reinterpret_cast<const float4*>(inp + idx4);
    *reinterpret_cast<__half2*>(g_ih + idx4)     = __floats2half2_rn(u.x, u.y);
    *reinterpret_cast<__half2*>(g_ih + idx4 + 2) = __floats2half2_rn(u.z, u.w);
}

__global__ void __launch_bounds__(NTHREADS, 2)
dynlin_main_kernel(const float* __restrict__ wv,
                   const float* __restrict__ biases,
                   float* __restrict__ out)
{
    extern __shared__ char sm[];
    const uint32_t sb = smem_u32(sm);
    const int tid  = threadIdx.x;
    const int lane = tid & 31;
    const int wid  = tid >> 5;
    const int wm   = wid & 1;          // 2 warp rows x 32
    const int wn   = wid >> 1;         // 2 warp cols x 64
    const int bx   = blockIdx.x;
    const int col0 = bx * TN;
    const int row0 = blockIdx.y * TM;

    const uint32_t mb_full  = sb + SM_MBAR;       // full[0], full[1] (tx-based, count 1)
    const uint32_t mb_empty = sb + SM_MBAR + 16;  // empty[0], empty[1] (count 128)

    if (tid == 0) {
        asm volatile("mbarrier.init.shared.b64 [%0], 1;"  :: "r"(mb_full)      : "memory");
        asm volatile("mbarrier.init.shared.b64 [%0], 1;"  :: "r"(mb_full + 8)  : "memory");
        asm volatile("mbarrier.init.shared.b64 [%0], %1;" :: "r"(mb_empty),     "r"(NTHREADS) : "memory");
        asm volatile("mbarrier.init.shared.b64 [%0], %1;" :: "r"(mb_empty + 8), "r"(NTHREADS) : "memory");
    }
    __syncthreads();   // init visible before any arrive/wait

    // prologue: pair 0 into buffer 0, single bulk copy
    const char* wt0 = reinterpret_cast<const char*>(g_wt);
    if (tid == 0) {
        mbar_expect_tx(mb_full, 32768u);
        bulk_cp(sb + SM_B, wt0 + ((size_t)bx << 15), 32768u, mb_full);
    }

    {   // bias tile [8][128]
        int d = tid >> 4, c = (tid & 15) * 8;
        float4 b0 = *reinterpret_cast<const float4*>(biases + (size_t)d * OUTD + col0 + c);
        float4 b1 = *reinterpret_cast<const float4*>(biases + (size_t)d * OUTD + col0 + c + 4);
        *reinterpret_cast<float4*>(sm + SM_BIAS + (d * TN + c) * 4)     = b0;
        *reinterpret_cast<float4*>(sm + SM_BIAS + (d * TN + c + 4) * 4) = b1;
    }

    float wr[2][2][8];
    #pragma unroll
    for (int mt = 0; mt < 2; mt++)
        #pragma unroll
        for (int rs = 0; rs < 2; rs++) {
            int r = row0 + wm * 32 + mt * 16 + rs * 8 + (lane >> 2);
            float4 w0 = *reinterpret_cast<const float4*>(wv + (size_t)r * DD);
            float4 w1 = *reinterpret_cast<const float4*>(wv + (size_t)r * DD + 4);
            wr[mt][rs][0]=w0.x; wr[mt][rs][1]=w0.y; wr[mt][rs][2]=w0.z; wr[mt][rs][3]=w0.w;
            wr[mt][rs][4]=w1.x; wr[mt][rs][5]=w1.y; wr[mt][rs][6]=w1.z; wr[mt][rs][7]=w1.w;
        }

    float acc[2][8][4];
    #pragma unroll
    for (int mt = 0; mt < 2; mt++)
        #pragma unroll
        for (int nt = 0; nt < 8; nt++)
            #pragma unroll
            for (int k = 0; k < 4; k++) acc[mt][nt][k] = 0.f;

    // per-thread input base pointers (2 rows)
    const __half* iprow[2][2];
    #pragma unroll
    for (int mt = 0; mt < 2; mt++)
        #pragma unroll
        for (int rs = 0; rs < 2; rs++) {
            int r = row0 + wm * 32 + mt * 16 + rs * 8 + (lane >> 2);
            iprow[mt][rs] = g_ih + (size_t)r * IND + (lane & 3) * 2;
        }

    uint32_t inch[2][4][2][2];     // current ic input (half2)
    uint32_t inch_nx[2][4][2][2];  // prefetched next ic

    // initial load for ic = 0
    #pragma unroll
    for (int mt = 0; mt < 2; mt++)
        #pragma unroll
        for (int rs = 0; rs < 2; rs++)
            #pragma unroll
            for (int kb = 0; kb < 4; kb++)
                #pragma unroll
                for (int hs = 0; hs < 2; hs++)
                    inch[mt][kb][rs][hs] = *reinterpret_cast<const uint32_t*>(
                        iprow[mt][rs] + kb * 16 + hs * 8);

    #pragma unroll 1
    for (int ic = 0; ic < NIC; ic++) {
        #pragma unroll
        for (int jp = 0; jp < 4; jp++) {
            const int j  = ic * 4 + jp;
            const int pb = jp & 1;
            const uint32_t pf = (uint32_t)((jp >> 1) & 1);                 // full[pb]
            const uint32_t pe = (uint32_t)((jp == 0 || jp == 3) ? 1 : 0);  // empty[pb^1]

            uint32_t whd[2][2][2];
            #pragma unroll
            for (int half = 0; half < 2; half++)
                #pragma unroll
                for (int mt = 0; mt < 2; mt++)
                    #pragma unroll
                    for (int rs = 0; rs < 2; rs++) {
                        __half2 h = __half2half2(__float2half_rn(wr[mt][rs][jp * 2 + half]));
                        whd[half][mt][rs] = *reinterpret_cast<uint32_t*>(&h);
                    }

            // producer (elected): fetch pair j+1 into buffer pb^1, one bulk copy
            if (tid == 0 && j + 1 < NPAIRS) {
                const int jj = j + 1;
                if (j >= 1) mbar_wait(mb_empty + (uint32_t)(pb ^ 1) * 8, pe);
                const uint32_t fb = mb_full + (uint32_t)(pb ^ 1) * 8;
                mbar_expect_tx(fb, 32768u);
                bulk_cp(sb + SM_B + (uint32_t)(pb ^ 1) * 32768,
                        wt0 + ((size_t)(jj * 8 + bx) << 15), 32768u, fb);
            }

            // consumer: wait pair j data
            mbar_wait(mb_full + (uint32_t)pb * 8, pf);

            // prefetch next ic's input under pair 3's MMA work
            if (jp == 3 && ic + 1 < NIC) {
                const int ioff = (ic + 1) * KC;
                #pragma unroll
                for (int mt = 0; mt < 2; mt++)
                    #pragma unroll
                    for (int rs = 0; rs < 2; rs++)
                        #pragma unroll
                        for (int kb = 0; kb < 4; kb++)
                            #pragma unroll
                            for (int hs = 0; hs < 2; hs++)
                                inch_nx[mt][kb][rs][hs] =
                                    *reinterpret_cast<const uint32_t*>(
                                        iprow[mt][rs] + ioff + kb * 16 + hs * 8);
            }

            #pragma unroll
            for (int half = 0; half < 2; half++) {
                const uint32_t bbase = sb + SM_B + (uint32_t)pb * 32768
                                     + (uint32_t)half * 16384;
                #pragma unroll
                for (int kb = 0; kb < 4; kb++) {
                    uint32_t bf[16];
                    #pragma unroll
                    for (int pr = 0; pr < 4; pr++) {
                        int n = wn * 64 + pr * 16 + (lane & 7) + ((lane >> 4) << 3);
                        uint32_t off = (uint32_t)(n * 128 + kb * 32 + ((lane >> 3) & 1) * 16);
                        off ^= (uint32_t)((n & 7) << 4);
                        ldsm4(bf + pr * 4, bbase + off);
                    }
                    #pragma unroll
                    for (int mt = 0; mt < 2; mt++) {
                        uint32_t a0 = hmul2u(inch[mt][kb][0][0], whd[half][mt][0]);
                        uint32_t a1 = hmul2u(inch[mt][kb][1][0], whd[half][mt][1]);
                        uint32_t a2 = hmul2u(inch[mt][kb][0][1], whd[half][mt][0]);
                        uint32_t a3 = hmul2u(inch[mt][kb][1][1], whd[half][mt][1]);
                        #pragma unroll
                        for (int nt = 0; nt < 8; nt++) {
                            int bi = (nt >> 1) * 4 + (nt & 1) * 2;
                            mma16816(acc[mt][nt], a0, a1, a2, a3, bf[bi], bf[bi + 1]);
                        }
                    }
                }
            }

            // reads of pair j done
            mbar_arrive(mb_empty + (uint32_t)pb * 8);
        }

        // rotate prefetched input into place (register moves)
        if (ic + 1 < NIC) {
            #pragma unroll
            for (int mt = 0; mt < 2; mt++)
                #pragma unroll
                for (int kb = 0; kb < 4; kb++)
                    #pragma unroll
                    for (int rs = 0; rs < 2; rs++)
                        #pragma unroll
                        for (int hs = 0; hs < 2; hs++)
                            inch[mt][kb][rs][hs] = inch_nx[mt][kb][rs][hs];
        }
    }

    __syncthreads();

    // epilogue: out = acc + sum_d w[row,d]*biases[d,col]
    #pragma unroll
    for (int nt = 0; nt < 8; nt++) {
        int coff = wn * 64 + nt * 8 + (lane & 3) * 2;
        float2 bv[8];
        #pragma unroll
        for (int d = 0; d < DD; d++)
            bv[d] = *reinterpret_cast<const float2*>(sm + SM_BIAS + (d * TN + coff) * 4);
        #pragma unroll
        for (int mt = 0; mt < 2; mt++)
            #pragma unroll
            for (int rs = 0; rs < 2; rs++) {
                float s0 = 0.f, s1 = 0.f;
                #pragma unroll
                for (int d = 0; d < DD; d++) {
                    s0 = fmaf(wr[mt][rs][d], bv[d].x, s0);
                    s1 = fmaf(wr[mt][rs][d], bv[d].y, s1);
                }
                int r = row0 + wm * 32 + mt * 16 + rs * 8 + (lane >> 2);
                float2 o;
                o.x = acc[mt][nt][rs * 2 + 0] + s0;
                o.y = acc[mt][nt][rs * 2 + 1] + s1;
                *reinterpret_cast<float2*>(out + (size_t)r * OUTD + col0 + coff) = o;
            }
    }
}

extern "C" void kernel_launch(void* const* d_in, const int* in_sizes, int n_in,
                              void* d_out, int out_size) {
    const float* input = nullptr;
    const float* wv = nullptr;
    const float* weights = nullptr;
    const float* biases = nullptr;
    for (int i = 0; i < n_in; i++) {
        long long sz = in_sizes[i];
        if (sz == (long long)BATCH * DD)           wv = (const float*)d_in[i];
        else if (sz == (long long)DD * OUTD)       biases = (const float*)d_in[i];
        else if (sz == (long long)BATCH * IND) {
            if (!input) input = (const float*)d_in[i];
            else        weights = (const float*)d_in[i];
        }
    }
    float* out = (float*)d_out;

    dynlin_prep_kernel<<<(DD * OUTD * IND) / (256 * 4), 256>>>(weights, input);

    cudaFuncSetAttribute(dynlin_main_kernel,
                         cudaFuncAttributeMaxDynamicSharedMemorySize, SM_ALLOC);
    dim3 grid(OUTD / TN, BATCH / TM);
    dynlin_main_kernel<<<grid, NTHREADS, SM_ALLOC>>>(wv, biases, out);
}